// round 1
// baseline (speedup 1.0000x reference)
#include <cuda_runtime.h>
#include <cstdint>

// Problem constants (fixed shapes from reference)
#define NPTS 131072
#define BATCH 16
#define CDIM 512
#define CH   128    // attention hidden = C/4
#define FUSE 1056   // 2C + EMB
#define H1   256
#define H2   128
#define EMB  32

// Scratch (device globals — no allocation allowed)
__device__ float g_scores[2][NPTS];
__device__ float g_wgt[2][NPTS];
__device__ float g_part[2][BATCH][8][CDIM];
__device__ float g_pool[2][BATCH][CDIM];

// ---------- packed f32x2 helpers ----------
__device__ __forceinline__ void fma2(unsigned long long& d, unsigned long long a, unsigned long long b) {
    asm("fma.rn.f32x2 %0, %1, %2, %0;" : "+l"(d) : "l"(a), "l"(b));
}
__device__ __forceinline__ unsigned long long splat2(float x) {
    unsigned long long r;
    asm("mov.b64 %0, {%1, %1};" : "=l"(r) : "f"(x));
    return r;
}
__device__ __forceinline__ unsigned long long pack2(float x, float y) {
    unsigned long long r;
    asm("mov.b64 %0, {%1, %2};" : "=l"(r) : "f"(x), "f"(y));
    return r;
}
__device__ __forceinline__ float2 unpack2(unsigned long long v) {
    float2 f;
    asm("mov.b64 {%0, %1}, %2;" : "=f"(f.x), "=f"(f.y) : "l"(v));
    return f;
}

// ============================================================================
// K1: fused scores GEMM.  scores[m] = relu(feat[m,:] @ w1 + b1) @ w2 + b2
// Tile: 128 rows x 128 hidden (full), K=512 in chunks of 16.
// 256 threads (16x16), each owns 8x8 outputs packed as 8x4 f32x2 accumulators.
// ============================================================================
__global__ __launch_bounds__(256, 2) void scores_kernel(
    const float* __restrict__ feat,
    const float* __restrict__ w1, const float* __restrict__ b1,
    const float* __restrict__ w2, const float* __restrict__ b2,
    int t)
{
    __shared__ __align__(16) unsigned long long As[16][132]; // splatted feat values
    __shared__ __align__(16) unsigned long long Bs[16][64];  // packed w1 col-pairs
    __shared__ float sb1[CH], sw2[CH];

    const int tid = threadIdx.x;
    const int tx = tid & 15, ty = tid >> 4;
    const int rowBase = blockIdx.x * 128;

    if (tid < CH) { sb1[tid] = b1[tid]; sw2[tid] = w2[tid]; }

    unsigned long long acc[8][4];
#pragma unroll
    for (int i = 0; i < 8; i++)
#pragma unroll
        for (int j = 0; j < 4; j++) acc[i][j] = 0ULL;

    for (int ko = 0; ko < CDIM; ko += 16) {
        __syncthreads();
        // feat tile: 128 rows x 16 k  (512 float4 loads, 2 per thread)
#pragma unroll
        for (int u = 0; u < 2; u++) {
            int l = tid * 2 + u;
            int row = l >> 2;
            int kq = (l & 3) * 4;
            float4 v = *(const float4*)(feat + (size_t)(rowBase + row) * CDIM + ko + kq);
            As[kq + 0][row] = splat2(v.x);
            As[kq + 1][row] = splat2(v.y);
            As[kq + 2][row] = splat2(v.z);
            As[kq + 3][row] = splat2(v.w);
        }
        // w1 tile: 16 k-rows x 128 cols (512 float4 loads, 2 per thread)
#pragma unroll
        for (int u = 0; u < 2; u++) {
            int l = tid * 2 + u;
            int kr = l >> 5;
            int c4 = (l & 31) * 4;
            float4 v = *(const float4*)(w1 + (size_t)(ko + kr) * CH + c4);
            Bs[kr][(c4 >> 1) + 0] = pack2(v.x, v.y);
            Bs[kr][(c4 >> 1) + 1] = pack2(v.z, v.w);
        }
        __syncthreads();
#pragma unroll
        for (int kk = 0; kk < 16; kk++) {
            unsigned long long a[8], b[4];
            *(ulonglong2*)&a[0] = *(const ulonglong2*)&As[kk][ty * 8 + 0];
            *(ulonglong2*)&a[2] = *(const ulonglong2*)&As[kk][ty * 8 + 2];
            *(ulonglong2*)&a[4] = *(const ulonglong2*)&As[kk][ty * 8 + 4];
            *(ulonglong2*)&a[6] = *(const ulonglong2*)&As[kk][ty * 8 + 6];
            *(ulonglong2*)&b[0] = *(const ulonglong2*)&Bs[kk][tx * 4 + 0];
            *(ulonglong2*)&b[2] = *(const ulonglong2*)&Bs[kk][tx * 4 + 2];
#pragma unroll
            for (int i = 0; i < 8; i++)
#pragma unroll
                for (int j = 0; j < 4; j++)
                    fma2(acc[i][j], a[i], b[j]);
        }
    }

    // Epilogue: relu(+b1) dot w2, reduce across tx, write scores
    const float bias = b2[0];
#pragma unroll
    for (int i = 0; i < 8; i++) {
        float s = 0.f;
#pragma unroll
        for (int j = 0; j < 4; j++) {
            float2 v = unpack2(acc[i][j]);
            int c = tx * 8 + j * 2;
            float h0 = v.x + sb1[c];     h0 = h0 > 0.f ? h0 : 0.f;
            float h1 = v.y + sb1[c + 1]; h1 = h1 > 0.f ? h1 : 0.f;
            s += h0 * sw2[c] + h1 * sw2[c + 1];
        }
        s += __shfl_xor_sync(0xffffffffu, s, 1);
        s += __shfl_xor_sync(0xffffffffu, s, 2);
        s += __shfl_xor_sync(0xffffffffu, s, 4);
        s += __shfl_xor_sync(0xffffffffu, s, 8);
        if (tx == 0) g_scores[t][rowBase + ty * 8 + i] = s + bias;
    }
}

// ============================================================================
// K2: per-segment softmax stats + weight write.  grid (BATCH, 2)
// ============================================================================
__global__ __launch_bounds__(256) void seg_softmax_kernel(
    const int* __restrict__ loff, const int* __restrict__ poff)
{
    const int b = blockIdx.x;
    const int t = blockIdx.y;
    const int* off = t ? poff : loff;
    const int start = b ? off[b - 1] : 0;
    const int end = off[b];
    const float* sc = g_scores[t];
    float* wg = g_wgt[t];
    __shared__ float red[256];
    const int tid = threadIdx.x;

    float m = -1e30f;
    for (int i = start + tid; i < end; i += 256) m = fmaxf(m, sc[i]);
    red[tid] = m; __syncthreads();
    for (int s2 = 128; s2 > 0; s2 >>= 1) {
        if (tid < s2) red[tid] = fmaxf(red[tid], red[tid + s2]);
        __syncthreads();
    }
    m = red[0]; __syncthreads();

    float s = 0.f;
    for (int i = start + tid; i < end; i += 256) s += expf(sc[i] - m);
    red[tid] = s; __syncthreads();
    for (int s2 = 128; s2 > 0; s2 >>= 1) {
        if (tid < s2) red[tid] += red[tid + s2];
        __syncthreads();
    }
    const float inv = 1.f / red[0];
    for (int i = start + tid; i < end; i += 256)
        wg[i] = expf(sc[i] - m) * inv;
}

// ============================================================================
// K3: weighted pooling partials.  grid (4 col-chunks, 8 point-slices, 32 b*t)
// Deterministic: each block writes its own partial slot; no atomics.
// ============================================================================
__global__ __launch_bounds__(128) void pool_kernel(
    const float* __restrict__ lf, const float* __restrict__ pf,
    const int* __restrict__ loff, const int* __restrict__ poff)
{
    const int q = blockIdx.x;       // col chunk 0..3
    const int sl = blockIdx.y;      // point slice 0..7
    const int bt = blockIdx.z;      // b*2 + t
    const int b = bt >> 1, t = bt & 1;
    const float* feat = t ? pf : lf;
    const int* off = t ? poff : loff;
    const int start = b ? off[b - 1] : 0;
    const int end = off[b];
    const int cnt = end - start;
    const int per = (cnt + 7) >> 3;
    const int i0 = start + sl * per;
    const int i1 = min(i0 + per, end);
    const int c = q * 128 + threadIdx.x;

    __shared__ float sw[128];
    float acc0 = 0.f, acc1 = 0.f;

    for (int ib = i0; ib < i1; ib += 128) {
        const int n = min(128, i1 - ib);
        __syncthreads();
        if (threadIdx.x < n) sw[threadIdx.x] = g_wgt[t][ib + threadIdx.x];
        __syncthreads();
#pragma unroll 8
        for (int k = 0; k < n; k += 2) {
            acc0 += feat[(size_t)(ib + k) * CDIM + c] * sw[k];
            if (k + 1 < n) acc1 += feat[(size_t)(ib + k + 1) * CDIM + c] * sw[k + 1];
        }
    }
    g_part[t][b][sl][c] = acc0 + acc1;
}

// K3b: reduce the 8 slices. grid 32 (b*t), block 512 (one channel each)
__global__ __launch_bounds__(512) void pool_reduce_kernel()
{
    const int bt = blockIdx.x;
    const int b = bt >> 1, t = bt & 1;
    const int c = threadIdx.x;
    float s = 0.f;
#pragma unroll
    for (int sl = 0; sl < 8; sl++) s += g_part[t][b][sl][c];
    g_pool[t][b][c] = s;
}

// ============================================================================
// K4: regression head. One block per batch row; LN is per-row so rows are
// independent.
// ============================================================================
__global__ __launch_bounds__(256) void head_kernel(
    const int* __restrict__ cat_id, const float* __restrict__ cat_emb,
    const float* __restrict__ rw1, const float* __restrict__ rb1,
    const float* __restrict__ g1, const float* __restrict__ be1,
    const float* __restrict__ rw2, const float* __restrict__ rb2,
    const float* __restrict__ g2, const float* __restrict__ be2,
    const float* __restrict__ rw3, const float* __restrict__ rb3,
    float* __restrict__ out)
{
    const int b = blockIdx.x;
    const int tid = threadIdx.x;
    __shared__ float g[FUSE];
    __shared__ float h[H1];
    __shared__ float h2[H2];
    __shared__ float red[256];

    for (int i = tid; i < CDIM; i += 256) {
        g[i] = g_pool[0][b][i];
        g[CDIM + i] = g_pool[1][b][i];
    }
    if (tid < EMB) g[2 * CDIM + tid] = cat_emb[cat_id[b] * EMB + tid];
    __syncthreads();

    // ---- layer 1: t1 = g @ rw1 + rb1 (each thread one of 256 cols) ----
    float acc = rb1[tid];
    for (int k = 0; k < FUSE; k++) acc += g[k] * rw1[(size_t)k * H1 + tid];

    // LN over 256
    red[tid] = acc; __syncthreads();
    for (int s = 128; s > 0; s >>= 1) { if (tid < s) red[tid] += red[tid + s]; __syncthreads(); }
    float mu = red[0] / (float)H1; __syncthreads();
    red[tid] = acc * acc; __syncthreads();
    for (int s = 128; s > 0; s >>= 1) { if (tid < s) red[tid] += red[tid + s]; __syncthreads(); }
    float var = red[0] / (float)H1 - mu * mu;
    {
        float v = (acc - mu) * rsqrtf(var + 1e-5f) * g1[tid] + be1[tid];
        h[tid] = v > 0.f ? v : 0.f;
    }
    __syncthreads();

    // ---- layer 2: t2 = h @ rw2 + rb2 (threads < 128) ----
    float acc2 = 0.f;
    if (tid < H2) {
        acc2 = rb2[tid];
        for (int k = 0; k < H1; k++) acc2 += h[k] * rw2[(size_t)k * H2 + tid];
    }
    red[tid] = (tid < H2) ? acc2 : 0.f; __syncthreads();
    for (int s = 128; s > 0; s >>= 1) { if (tid < s) red[tid] += red[tid + s]; __syncthreads(); }
    mu = red[0] / (float)H2; __syncthreads();
    red[tid] = (tid < H2) ? acc2 * acc2 : 0.f; __syncthreads();
    for (int s = 128; s > 0; s >>= 1) { if (tid < s) red[tid] += red[tid + s]; __syncthreads(); }
    var = red[0] / (float)H2 - mu * mu;
    if (tid < H2) {
        float v = (acc2 - mu) * rsqrtf(var + 1e-5f) * g2[tid] + be2[tid];
        h2[tid] = v > 0.f ? v : 0.f;
    }
    __syncthreads();

    // ---- layer 3: out = h2 @ rw3 + rb3 ----
    if (tid < 3) {
        float o = rb3[tid];
        for (int k = 0; k < H2; k++) o += h2[k] * rw3[k * 3 + tid];
        out[b * 3 + tid] = o;
    }
}

// ============================================================================
extern "C" void kernel_launch(void* const* d_in, const int* in_sizes, int n_in,
                              void* d_out, int out_size)
{
    const float* local_feat  = (const float*)d_in[0];
    const float* parent_feat = (const float*)d_in[1];
    const int*   loff        = (const int*)d_in[2];
    const int*   poff        = (const int*)d_in[3];
    const int*   cat_id      = (const int*)d_in[4];
    const float* aw1 = (const float*)d_in[5];
    const float* ab1 = (const float*)d_in[6];
    const float* aw2 = (const float*)d_in[7];
    const float* ab2 = (const float*)d_in[8];
    const float* pw1 = (const float*)d_in[9];
    const float* pb1 = (const float*)d_in[10];
    const float* pw2 = (const float*)d_in[11];
    const float* pb2 = (const float*)d_in[12];
    const float* cemb = (const float*)d_in[13];
    const float* rw1 = (const float*)d_in[14];
    const float* rb1 = (const float*)d_in[15];
    const float* ln1g = (const float*)d_in[16];
    const float* ln1b = (const float*)d_in[17];
    const float* rw2 = (const float*)d_in[18];
    const float* rb2 = (const float*)d_in[19];
    const float* ln2g = (const float*)d_in[20];
    const float* ln2b = (const float*)d_in[21];
    const float* rw3 = (const float*)d_in[22];
    const float* rb3 = (const float*)d_in[23];

    const int nrows = in_sizes[0] / CDIM;      // 131072
    const int gridK1 = nrows / 128;            // 1024

    scores_kernel<<<gridK1, 256>>>(local_feat, aw1, ab1, aw2, ab2, 0);
    scores_kernel<<<gridK1, 256>>>(parent_feat, pw1, pb1, pw2, pb2, 1);
    seg_softmax_kernel<<<dim3(BATCH, 2), 256>>>(loff, poff);
    pool_kernel<<<dim3(4, 8, 2 * BATCH), 128>>>(local_feat, parent_feat, loff, poff);
    pool_reduce_kernel<<<2 * BATCH, 512>>>();
    head_kernel<<<BATCH, 256>>>(cat_id, cemb, rw1, rb1, ln1g, ln1b,
                                rw2, rb2, ln2g, ln2b, rw3, rb3, (float*)d_out);
}

// round 3
// speedup vs baseline: 2.6058x; 2.6058x over previous
#include <cuda_runtime.h>
#include <cuda_bf16.h>
#include <cstdint>

// Problem constants (fixed shapes)
#define NPTS 131072
#define BATCH 16
#define CDIM 512
#define CH   128
#define FUSE 1056
#define H1   256
#define H2   128
#define EMB  32
#define NSLICE 32

// Scratch (device globals — no allocation allowed)
__device__ float g_scores[2][NPTS];
__device__ float g_wgt[2][NPTS];
__device__ __align__(16) float g_part[2][BATCH][NSLICE][CDIM];
__device__ __align__(16) float g_pool[2][BATCH][CDIM];

// ---------------------------------------------------------------------------
// helpers
// ---------------------------------------------------------------------------
__device__ __forceinline__ uint32_t smem_u32(const void* p) {
    uint32_t a;
    asm("{ .reg .u64 t; cvta.to.shared.u64 t, %1; cvt.u32.u64 %0, t; }" : "=r"(a) : "l"(p));
    return a;
}

// byte offset into a [rows][64] bf16 tile (128B rows) with xor-swizzle on 16B units
__device__ __forceinline__ uint32_t swz(uint32_t row, uint32_t k) {
    return row * 128u + ((((k >> 3) ^ (row & 7)) & 7u) << 4) + (k & 7u) * 2u;
}

__device__ __forceinline__ void ldsm4(uint32_t* r, uint32_t addr) {
    asm volatile("ldmatrix.sync.aligned.m8n8.x4.shared.b16 {%0,%1,%2,%3}, [%4];"
        : "=r"(r[0]), "=r"(r[1]), "=r"(r[2]), "=r"(r[3]) : "r"(addr));
}

__device__ __forceinline__ void mma16816(float* c, const uint32_t* a, const uint32_t* b) {
    asm volatile("mma.sync.aligned.m16n8k16.row.col.f32.bf16.bf16.f32 "
        "{%0,%1,%2,%3}, {%4,%5,%6,%7}, {%8,%9}, {%0,%1,%2,%3};"
        : "+f"(c[0]), "+f"(c[1]), "+f"(c[2]), "+f"(c[3])
        : "r"(a[0]), "r"(a[1]), "r"(a[2]), "r"(a[3]), "r"(b[0]), "r"(b[1]));
}

__device__ __forceinline__ void split2(float x, uint16_t& h, uint16_t& l) {
    __nv_bfloat16 hb = __float2bfloat16_rn(x);
    float r = x - __bfloat162float(hb);
    __nv_bfloat16 lb = __float2bfloat16_rn(r);
    h = *reinterpret_cast<uint16_t*>(&hb);
    l = *reinterpret_cast<uint16_t*>(&lb);
}

// ---------------------------------------------------------------------------
// K1: HMMA scores GEMM.  scores[m] = relu(feat[m,:]@w1 + b1)@w2 + b2
// CTA: M=128 x N=128(hidden) x K=512 (8 chunks of 64). 8 warps, 64x32 each.
// fp32 accuracy via 2-term bf16 split (Ah*Bh + Ah*Bl + Al*Bh), fp32 accum.
// ---------------------------------------------------------------------------
#define SA_H  0
#define SA_L  16384
#define SB_H  32768
#define SB_L  49152
#define S_B1  65536
#define S_W2  66048
#define S_RED 66560
#define S_TOT 68608

__global__ void __launch_bounds__(256, 2) scores_mma_kernel(
    const float* __restrict__ lf, const float* __restrict__ pf,
    const float* __restrict__ aw1, const float* __restrict__ ab1,
    const float* __restrict__ aw2, const float* __restrict__ ab2,
    const float* __restrict__ pw1, const float* __restrict__ pb1,
    const float* __restrict__ pw2, const float* __restrict__ pb2)
{
    extern __shared__ char smem[];
    const int t = blockIdx.y;
    const float* feat = t ? pf : lf;
    const float* w1 = t ? pw1 : aw1;
    const float* b1 = t ? pb1 : ab1;
    const float* w2 = t ? pw2 : aw2;
    const float* b2 = t ? pb2 : ab2;

    const uint32_t sb = smem_u32(smem);
    const int tid = threadIdx.x;
    const int lane = tid & 31, wid = tid >> 5;
    const int warp_m = wid & 1, warp_n = wid >> 1;
    const int rowBase = blockIdx.x * 128;
    const int g = lane >> 2, tg = lane & 3;

    if (tid < CH) {
        ((float*)(smem + S_B1))[tid] = b1[tid];
        ((float*)(smem + S_W2))[tid] = w2[tid];
    }

    float c[4][4][4];
#pragma unroll
    for (int mi = 0; mi < 4; mi++)
#pragma unroll
        for (int ni = 0; ni < 4; ni++)
#pragma unroll
            for (int q = 0; q < 4; q++) c[mi][ni][q] = 0.f;

    // ldmatrix per-thread geometry
    const int a_r8 = lane & 7;
    const int a_msel = (lane >> 3) & 1;   // +8 rows for mats 1,3
    const int a_ksel = lane >> 4;         // +1 k-unit for mats 2,3
    const int b_r8 = lane & 7;
    const int b_nsel = (lane >> 4) & 1;   // +8 n for mats 2,3
    const int b_ksel = (lane >> 3) & 1;   // +1 k-unit for mats 1,3

    const int bn = tid & 127;             // B-load column
    const int bkh = (tid >> 7) * 2;       // B-load k sub-offset

    for (int c8 = 0; c8 < 8; c8++) {
        const int ko = c8 * 64;
        if (c8) __syncthreads();          // WAR: prior mma done before overwrite

        // ---- A tile: 128 rows x 64 k, hi/lo split ----
#pragma unroll
        for (int it = 0; it < 8; it++) {
            const int lin = it * 256 + tid;
            const int row = lin >> 4;
            const int kq = (lin & 15) * 4;
            float4 v = *(const float4*)(feat + (size_t)(rowBase + row) * CDIM + ko + kq);
            uint16_t h0, h1, h2, h3, l0, l1, l2, l3;
            split2(v.x, h0, l0); split2(v.y, h1, l1);
            split2(v.z, h2, l2); split2(v.w, h3, l3);
            const uint32_t off = swz(row, kq);
            *(uint2*)(smem + SA_H + off) =
                make_uint2((uint32_t)h0 | ((uint32_t)h1 << 16),
                           (uint32_t)h2 | ((uint32_t)h3 << 16));
            *(uint2*)(smem + SA_L + off) =
                make_uint2((uint32_t)l0 | ((uint32_t)l1 << 16),
                           (uint32_t)l2 | ((uint32_t)l3 << 16));
        }
        // ---- B tile: w1[ko..ko+64, :] transposed into [n=128][k=64] ----
#pragma unroll
        for (int kk = 0; kk < 16; kk++) {
            const int k0 = kk * 4 + bkh;
            float x0 = w1[(size_t)(ko + k0) * CH + bn];
            float x1 = w1[(size_t)(ko + k0 + 1) * CH + bn];
            uint16_t h0, h1, l0, l1;
            split2(x0, h0, l0); split2(x1, h1, l1);
            const uint32_t off = swz((uint32_t)bn, (uint32_t)k0);
            *(uint32_t*)(smem + SB_H + off) = (uint32_t)h0 | ((uint32_t)h1 << 16);
            *(uint32_t*)(smem + SB_L + off) = (uint32_t)l0 | ((uint32_t)l1 << 16);
        }
        __syncthreads();

        // ---- MMA over 4 k16 steps ----
#pragma unroll
        for (int ks = 0; ks < 4; ks++) {
            uint32_t bh[2][4], bl[2][4];
#pragma unroll
            for (int p = 0; p < 2; p++) {
                const uint32_t nn = (uint32_t)(warp_n * 32 + p * 16 + b_nsel * 8 + b_r8);
                const uint32_t ku = (uint32_t)(ks * 2 + b_ksel);
                const uint32_t off = nn * 128u + (((ku ^ (nn & 7)) & 7u) << 4);
                ldsm4(bh[p], sb + SB_H + off);
                ldsm4(bl[p], sb + SB_L + off);
            }
#pragma unroll
            for (int mi = 0; mi < 4; mi++) {
                const uint32_t rr = (uint32_t)(warp_m * 64 + mi * 16 + a_msel * 8 + a_r8);
                const uint32_t ku = (uint32_t)(ks * 2 + a_ksel);
                const uint32_t off = rr * 128u + (((ku ^ (rr & 7)) & 7u) << 4);
                uint32_t ah[4], al[4];
                ldsm4(ah, sb + SA_H + off);
                ldsm4(al, sb + SA_L + off);
#pragma unroll
                for (int ni = 0; ni < 4; ni++) {
                    const uint32_t* bhp = &bh[ni >> 1][(ni & 1) * 2];
                    const uint32_t* blp = &bl[ni >> 1][(ni & 1) * 2];
                    mma16816(c[mi][ni], ah, bhp);
                    mma16816(c[mi][ni], ah, blp);
                    mma16816(c[mi][ni], al, bhp);
                }
            }
        }
    }

    // ---- epilogue: relu(+b1) dot w2 per row, reduce across n ----
    const float* sb1 = (const float*)(smem + S_B1);
    const float* sw2 = (const float*)(smem + S_W2);
    float* sred = (float*)(smem + S_RED);
    const float bias2 = b2[0];

#pragma unroll
    for (int mi = 0; mi < 4; mi++) {
        float s0 = 0.f, s1 = 0.f;
#pragma unroll
        for (int ni = 0; ni < 4; ni++) {
            const int n0 = warp_n * 32 + ni * 8 + tg * 2;
            const float w20 = sw2[n0], w21 = sw2[n0 + 1];
            const float bb0 = sb1[n0], bb1 = sb1[n0 + 1];
            s0 += fmaxf(c[mi][ni][0] + bb0, 0.f) * w20;
            s0 += fmaxf(c[mi][ni][1] + bb1, 0.f) * w21;
            s1 += fmaxf(c[mi][ni][2] + bb0, 0.f) * w20;
            s1 += fmaxf(c[mi][ni][3] + bb1, 0.f) * w21;
        }
        s0 += __shfl_xor_sync(0xffffffffu, s0, 1);
        s0 += __shfl_xor_sync(0xffffffffu, s0, 2);
        s1 += __shfl_xor_sync(0xffffffffu, s1, 1);
        s1 += __shfl_xor_sync(0xffffffffu, s1, 2);
        if (tg == 0) {
            const int r0 = warp_m * 64 + mi * 16 + g;
            sred[warp_n * 128 + r0] = s0;
            sred[warp_n * 128 + r0 + 8] = s1;
        }
    }
    __syncthreads();
    if (tid < 128) {
        float s = sred[tid] + sred[128 + tid] + sred[256 + tid] + sred[384 + tid];
        g_scores[t][rowBase + tid] = s + bias2;
    }
}

// ---------------------------------------------------------------------------
// K2: per-segment softmax stats + weight write.  grid (BATCH, 2)
// ---------------------------------------------------------------------------
__global__ __launch_bounds__(256) void seg_softmax_kernel(
    const int* __restrict__ loff, const int* __restrict__ poff)
{
    const int b = blockIdx.x;
    const int t = blockIdx.y;
    const int* off = t ? poff : loff;
    const int start = b ? off[b - 1] : 0;
    const int end = off[b];
    const float* sc = g_scores[t];
    float* wg = g_wgt[t];
    __shared__ float red[256];
    const int tid = threadIdx.x;

    float m = -1e30f;
    for (int i = start + tid; i < end; i += 256) m = fmaxf(m, sc[i]);
    red[tid] = m; __syncthreads();
    for (int s2 = 128; s2 > 0; s2 >>= 1) {
        if (tid < s2) red[tid] = fmaxf(red[tid], red[tid + s2]);
        __syncthreads();
    }
    m = red[0]; __syncthreads();

    float s = 0.f;
    for (int i = start + tid; i < end; i += 256) s += expf(sc[i] - m);
    red[tid] = s; __syncthreads();
    for (int s2 = 128; s2 > 0; s2 >>= 1) {
        if (tid < s2) red[tid] += red[tid + s2];
        __syncthreads();
    }
    const float inv = 1.f / red[0];
    for (int i = start + tid; i < end; i += 256)
        wg[i] = expf(sc[i] - m) * inv;
}

// ---------------------------------------------------------------------------
// K3: weighted pooling partials. grid (NSLICE, 2*BATCH), block 128.
// Each thread owns 4 channels (float4); weights staged in SMEM.
// ---------------------------------------------------------------------------
__global__ __launch_bounds__(128) void pool_kernel(
    const float* __restrict__ lf, const float* __restrict__ pf,
    const int* __restrict__ loff, const int* __restrict__ poff)
{
    const int sl = blockIdx.x;
    const int bt = blockIdx.y;
    const int b = bt >> 1, t = bt & 1;
    const float* feat = t ? pf : lf;
    const int* off = t ? poff : loff;
    const int start = b ? off[b - 1] : 0;
    const int end = off[b];
    const int cnt = end - start;
    const int per = (cnt + NSLICE - 1) / NSLICE;
    const int i0 = start + sl * per;
    const int i1 = min(i0 + per, end);
    const int c = threadIdx.x * 4;

    __shared__ float sw[256];
    float4 acc = make_float4(0.f, 0.f, 0.f, 0.f);

    for (int base = i0; base < i1; base += 256) {
        const int n = min(256, i1 - base);
        __syncthreads();
        for (int i = threadIdx.x; i < n; i += 128) sw[i] = g_wgt[t][base + i];
        __syncthreads();
        int r = 0;
        for (; r + 4 <= n; r += 4) {
            const float* p0 = feat + (size_t)(base + r) * CDIM + c;
            float4 v0 = *(const float4*)(p0);
            float4 v1 = *(const float4*)(p0 + CDIM);
            float4 v2 = *(const float4*)(p0 + 2 * CDIM);
            float4 v3 = *(const float4*)(p0 + 3 * CDIM);
            const float w0 = sw[r], w1_ = sw[r + 1], w2_ = sw[r + 2], w3 = sw[r + 3];
            acc.x += v0.x * w0 + v1.x * w1_ + v2.x * w2_ + v3.x * w3;
            acc.y += v0.y * w0 + v1.y * w1_ + v2.y * w2_ + v3.y * w3;
            acc.z += v0.z * w0 + v1.z * w1_ + v2.z * w2_ + v3.z * w3;
            acc.w += v0.w * w0 + v1.w * w1_ + v2.w * w2_ + v3.w * w3;
        }
        for (; r < n; r++) {
            float4 v = *(const float4*)(feat + (size_t)(base + r) * CDIM + c);
            const float w = sw[r];
            acc.x += v.x * w; acc.y += v.y * w; acc.z += v.z * w; acc.w += v.w * w;
        }
    }
    *(float4*)&g_part[t][b][sl][c] = acc;
}

// K3b: reduce slices. grid 2*BATCH, block 512.
__global__ __launch_bounds__(512) void pool_reduce_kernel()
{
    const int bt = blockIdx.x;
    const int b = bt >> 1, t = bt & 1;
    const int c = threadIdx.x;
    float s = 0.f;
#pragma unroll
    for (int sl = 0; sl < NSLICE; sl++) s += g_part[t][b][sl][c];
    g_pool[t][b][c] = s;
}

// ---------------------------------------------------------------------------
// K4: regression head. One block per batch row.
// ---------------------------------------------------------------------------
__global__ __launch_bounds__(256) void head_kernel(
    const int* __restrict__ cat_id, const float* __restrict__ cat_emb,
    const float* __restrict__ rw1, const float* __restrict__ rb1,
    const float* __restrict__ g1, const float* __restrict__ be1,
    const float* __restrict__ rw2, const float* __restrict__ rb2,
    const float* __restrict__ g2, const float* __restrict__ be2,
    const float* __restrict__ rw3, const float* __restrict__ rb3,
    float* __restrict__ out)
{
    const int b = blockIdx.x;
    const int tid = threadIdx.x;
    __shared__ float g[FUSE];
    __shared__ float h[H1];
    __shared__ float h2[H2];
    __shared__ float red[256];

    for (int i = tid; i < CDIM; i += 256) {
        g[i] = g_pool[0][b][i];
        g[CDIM + i] = g_pool[1][b][i];
    }
    if (tid < EMB) g[2 * CDIM + tid] = cat_emb[cat_id[b] * EMB + tid];
    __syncthreads();

    float acc = rb1[tid];
    for (int k = 0; k < FUSE; k++) acc += g[k] * rw1[(size_t)k * H1 + tid];

    red[tid] = acc; __syncthreads();
    for (int s = 128; s > 0; s >>= 1) { if (tid < s) red[tid] += red[tid + s]; __syncthreads(); }
    float mu = red[0] / (float)H1; __syncthreads();
    red[tid] = acc * acc; __syncthreads();
    for (int s = 128; s > 0; s >>= 1) { if (tid < s) red[tid] += red[tid + s]; __syncthreads(); }
    float var = red[0] / (float)H1 - mu * mu;
    {
        float v = (acc - mu) * rsqrtf(var + 1e-5f) * g1[tid] + be1[tid];
        h[tid] = v > 0.f ? v : 0.f;
    }
    __syncthreads();

    float acc2 = 0.f;
    if (tid < H2) {
        acc2 = rb2[tid];
        for (int k = 0; k < H1; k++) acc2 += h[k] * rw2[(size_t)k * H2 + tid];
    }
    red[tid] = (tid < H2) ? acc2 : 0.f; __syncthreads();
    for (int s = 128; s > 0; s >>= 1) { if (tid < s) red[tid] += red[tid + s]; __syncthreads(); }
    mu = red[0] / (float)H2; __syncthreads();
    red[tid] = (tid < H2) ? acc2 * acc2 : 0.f; __syncthreads();
    for (int s = 128; s > 0; s >>= 1) { if (tid < s) red[tid] += red[tid + s]; __syncthreads(); }
    var = red[0] / (float)H2 - mu * mu;
    if (tid < H2) {
        float v = (acc2 - mu) * rsqrtf(var + 1e-5f) * g2[tid] + be2[tid];
        h2[tid] = v > 0.f ? v : 0.f;
    }
    __syncthreads();

    if (tid < 3) {
        float o = rb3[tid];
        for (int k = 0; k < H2; k++) o += h2[k] * rw3[k * 3 + tid];
        out[b * 3 + tid] = o;
    }
}

// ---------------------------------------------------------------------------
extern "C" void kernel_launch(void* const* d_in, const int* in_sizes, int n_in,
                              void* d_out, int out_size)
{
    const float* local_feat  = (const float*)d_in[0];
    const float* parent_feat = (const float*)d_in[1];
    const int*   loff        = (const int*)d_in[2];
    const int*   poff        = (const int*)d_in[3];
    const int*   cat_id      = (const int*)d_in[4];
    const float* aw1 = (const float*)d_in[5];
    const float* ab1 = (const float*)d_in[6];
    const float* aw2 = (const float*)d_in[7];
    const float* ab2 = (const float*)d_in[8];
    const float* pw1 = (const float*)d_in[9];
    const float* pb1 = (const float*)d_in[10];
    const float* pw2 = (const float*)d_in[11];
    const float* pb2 = (const float*)d_in[12];
    const float* cemb = (const float*)d_in[13];
    const float* rw1 = (const float*)d_in[14];
    const float* rb1 = (const float*)d_in[15];
    const float* ln1g = (const float*)d_in[16];
    const float* ln1b = (const float*)d_in[17];
    const float* rw2 = (const float*)d_in[18];
    const float* rb2 = (const float*)d_in[19];
    const float* ln2g = (const float*)d_in[20];
    const float* ln2b = (const float*)d_in[21];
    const float* rw3 = (const float*)d_in[22];
    const float* rb3 = (const float*)d_in[23];

    const int nrows = in_sizes[0] / CDIM;   // 131072
    const int gridM = nrows / 128;          // 1024

    cudaFuncSetAttribute(scores_mma_kernel,
                         cudaFuncAttributeMaxDynamicSharedMemorySize, S_TOT);

    scores_mma_kernel<<<dim3(gridM, 2), 256, S_TOT>>>(
        local_feat, parent_feat,
        aw1, ab1, aw2, ab2, pw1, pb1, pw2, pb2);
    seg_softmax_kernel<<<dim3(BATCH, 2), 256>>>(loff, poff);
    pool_kernel<<<dim3(NSLICE, 2 * BATCH), 128>>>(local_feat, parent_feat, loff, poff);
    pool_reduce_kernel<<<2 * BATCH, 512>>>();
    head_kernel<<<BATCH, 256>>>(cat_id, cemb, rw1, rb1, ln1g, ln1b,
                                rw2, rb2, ln2g, ln2b, rw3, rb3, (float*)d_out);
}

// round 4
// speedup vs baseline: 2.6119x; 1.0023x over previous
#include <cuda_runtime.h>
#include <cuda_bf16.h>
#include <cstdint>

// Problem constants (fixed shapes)
#define NPTS 131072
#define BATCH 16
#define CDIM 512
#define CH   128
#define FUSE 1056
#define H1   256
#define H2   128
#define EMB  32
#define NSLICE 32

// Scratch (device globals — no allocation allowed)
__device__ float g_scores[2][NPTS];
__device__ float g_wgt[2][NPTS];
__device__ __align__(16) float g_part[2][BATCH][NSLICE][CDIM];
__device__ __align__(16) float g_pool[2][BATCH][CDIM];

// ---------------------------------------------------------------------------
// helpers
// ---------------------------------------------------------------------------
__device__ __forceinline__ uint32_t smem_u32(const void* p) {
    uint32_t a;
    asm("{ .reg .u64 t; cvta.to.shared.u64 t, %1; cvt.u32.u64 %0, t; }" : "=r"(a) : "l"(p));
    return a;
}

// byte offset into a [rows][64] bf16 tile (128B rows) with xor-swizzle on 16B units
__device__ __forceinline__ uint32_t swz(uint32_t row, uint32_t k) {
    return row * 128u + ((((k >> 3) ^ (row & 7)) & 7u) << 4) + (k & 7u) * 2u;
}

__device__ __forceinline__ void ldsm4(uint32_t* r, uint32_t addr) {
    asm volatile("ldmatrix.sync.aligned.m8n8.x4.shared.b16 {%0,%1,%2,%3}, [%4];"
        : "=r"(r[0]), "=r"(r[1]), "=r"(r[2]), "=r"(r[3]) : "r"(addr));
}

__device__ __forceinline__ void mma16816(float* c, const uint32_t* a, const uint32_t* b) {
    asm volatile("mma.sync.aligned.m16n8k16.row.col.f32.bf16.bf16.f32 "
        "{%0,%1,%2,%3}, {%4,%5,%6,%7}, {%8,%9}, {%0,%1,%2,%3};"
        : "+f"(c[0]), "+f"(c[1]), "+f"(c[2]), "+f"(c[3])
        : "r"(a[0]), "r"(a[1]), "r"(a[2]), "r"(a[3]), "r"(b[0]), "r"(b[1]));
}

__device__ __forceinline__ void split2(float x, uint16_t& h, uint16_t& l) {
    __nv_bfloat16 hb = __float2bfloat16_rn(x);
    float r = x - __bfloat162float(hb);
    __nv_bfloat16 lb = __float2bfloat16_rn(r);
    h = *reinterpret_cast<uint16_t*>(&hb);
    l = *reinterpret_cast<uint16_t*>(&lb);
}

// ---------------------------------------------------------------------------
// K1: HMMA scores GEMM.  scores[m] = relu(feat[m,:]@w1 + b1)@w2 + b2
// CTA: M=128 x N=128(hidden) x K=512 (8 chunks of 64). 8 warps, 64x32 each.
// fp32 accuracy via 2-term bf16 split (Ah*Bh + Ah*Bl + Al*Bh), fp32 accum.
// ---------------------------------------------------------------------------
#define SA_H  0
#define SA_L  16384
#define SB_H  32768
#define SB_L  49152
#define S_B1  65536
#define S_W2  66048
#define S_RED 66560
#define S_TOT 68608

__global__ void __launch_bounds__(256, 2) scores_mma_kernel(
    const float* __restrict__ lf, const float* __restrict__ pf,
    const float* __restrict__ aw1, const float* __restrict__ ab1,
    const float* __restrict__ aw2, const float* __restrict__ ab2,
    const float* __restrict__ pw1, const float* __restrict__ pb1,
    const float* __restrict__ pw2, const float* __restrict__ pb2)
{
    extern __shared__ char smem[];
    const int t = blockIdx.y;
    const float* feat = t ? pf : lf;
    const float* w1 = t ? pw1 : aw1;
    const float* b1 = t ? pb1 : ab1;
    const float* w2 = t ? pw2 : aw2;
    const float* b2 = t ? pb2 : ab2;

    const uint32_t sb = smem_u32(smem);
    const int tid = threadIdx.x;
    const int lane = tid & 31, wid = tid >> 5;
    const int warp_m = wid & 1, warp_n = wid >> 1;
    const int rowBase = blockIdx.x * 128;
    const int g = lane >> 2, tg = lane & 3;

    if (tid < CH) {
        ((float*)(smem + S_B1))[tid] = b1[tid];
        ((float*)(smem + S_W2))[tid] = w2[tid];
    }

    float c[4][4][4];
#pragma unroll
    for (int mi = 0; mi < 4; mi++)
#pragma unroll
        for (int ni = 0; ni < 4; ni++)
#pragma unroll
            for (int q = 0; q < 4; q++) c[mi][ni][q] = 0.f;

    // ldmatrix per-thread geometry
    const int a_r8 = lane & 7;
    const int a_msel = (lane >> 3) & 1;   // +8 rows for mats 1,3
    const int a_ksel = lane >> 4;         // +1 k-unit for mats 2,3
    const int b_r8 = lane & 7;
    const int b_nsel = (lane >> 4) & 1;   // +8 n for mats 2,3
    const int b_ksel = (lane >> 3) & 1;   // +1 k-unit for mats 1,3

    const int bn = tid & 127;             // B-load column
    const int bkh = (tid >> 7) * 2;       // B-load k sub-offset

    for (int c8 = 0; c8 < 8; c8++) {
        const int ko = c8 * 64;
        if (c8) __syncthreads();          // WAR: prior mma done before overwrite

        // ---- A tile: 128 rows x 64 k, hi/lo split ----
#pragma unroll
        for (int it = 0; it < 8; it++) {
            const int lin = it * 256 + tid;
            const int row = lin >> 4;
            const int kq = (lin & 15) * 4;
            float4 v = *(const float4*)(feat + (size_t)(rowBase + row) * CDIM + ko + kq);
            uint16_t h0, h1, h2, h3, l0, l1, l2, l3;
            split2(v.x, h0, l0); split2(v.y, h1, l1);
            split2(v.z, h2, l2); split2(v.w, h3, l3);
            const uint32_t off = swz(row, kq);
            *(uint2*)(smem + SA_H + off) =
                make_uint2((uint32_t)h0 | ((uint32_t)h1 << 16),
                           (uint32_t)h2 | ((uint32_t)h3 << 16));
            *(uint2*)(smem + SA_L + off) =
                make_uint2((uint32_t)l0 | ((uint32_t)l1 << 16),
                           (uint32_t)l2 | ((uint32_t)l3 << 16));
        }
        // ---- B tile: w1[ko..ko+64, :] transposed into [n=128][k=64] ----
#pragma unroll
        for (int kk = 0; kk < 16; kk++) {
            const int k0 = kk * 4 + bkh;
            float x0 = w1[(size_t)(ko + k0) * CH + bn];
            float x1 = w1[(size_t)(ko + k0 + 1) * CH + bn];
            uint16_t h0, h1, l0, l1;
            split2(x0, h0, l0); split2(x1, h1, l1);
            const uint32_t off = swz((uint32_t)bn, (uint32_t)k0);
            *(uint32_t*)(smem + SB_H + off) = (uint32_t)h0 | ((uint32_t)h1 << 16);
            *(uint32_t*)(smem + SB_L + off) = (uint32_t)l0 | ((uint32_t)l1 << 16);
        }
        __syncthreads();

        // ---- MMA over 4 k16 steps ----
#pragma unroll
        for (int ks = 0; ks < 4; ks++) {
            uint32_t bh[2][4], bl[2][4];
#pragma unroll
            for (int p = 0; p < 2; p++) {
                const uint32_t nn = (uint32_t)(warp_n * 32 + p * 16 + b_nsel * 8 + b_r8);
                const uint32_t ku = (uint32_t)(ks * 2 + b_ksel);
                const uint32_t off = nn * 128u + (((ku ^ (nn & 7)) & 7u) << 4);
                ldsm4(bh[p], sb + SB_H + off);
                ldsm4(bl[p], sb + SB_L + off);
            }
#pragma unroll
            for (int mi = 0; mi < 4; mi++) {
                const uint32_t rr = (uint32_t)(warp_m * 64 + mi * 16 + a_msel * 8 + a_r8);
                const uint32_t ku = (uint32_t)(ks * 2 + a_ksel);
                const uint32_t off = rr * 128u + (((ku ^ (rr & 7)) & 7u) << 4);
                uint32_t ah[4], al[4];
                ldsm4(ah, sb + SA_H + off);
                ldsm4(al, sb + SA_L + off);
#pragma unroll
                for (int ni = 0; ni < 4; ni++) {
                    const uint32_t* bhp = &bh[ni >> 1][(ni & 1) * 2];
                    const uint32_t* blp = &bl[ni >> 1][(ni & 1) * 2];
                    mma16816(c[mi][ni], ah, bhp);
                    mma16816(c[mi][ni], ah, blp);
                    mma16816(c[mi][ni], al, bhp);
                }
            }
        }
    }

    // ---- epilogue: relu(+b1) dot w2 per row, reduce across n ----
    const float* sb1 = (const float*)(smem + S_B1);
    const float* sw2 = (const float*)(smem + S_W2);
    float* sred = (float*)(smem + S_RED);
    const float bias2 = b2[0];

#pragma unroll
    for (int mi = 0; mi < 4; mi++) {
        float s0 = 0.f, s1 = 0.f;
#pragma unroll
        for (int ni = 0; ni < 4; ni++) {
            const int n0 = warp_n * 32 + ni * 8 + tg * 2;
            const float w20 = sw2[n0], w21 = sw2[n0 + 1];
            const float bb0 = sb1[n0], bb1 = sb1[n0 + 1];
            s0 += fmaxf(c[mi][ni][0] + bb0, 0.f) * w20;
            s0 += fmaxf(c[mi][ni][1] + bb1, 0.f) * w21;
            s1 += fmaxf(c[mi][ni][2] + bb0, 0.f) * w20;
            s1 += fmaxf(c[mi][ni][3] + bb1, 0.f) * w21;
        }
        s0 += __shfl_xor_sync(0xffffffffu, s0, 1);
        s0 += __shfl_xor_sync(0xffffffffu, s0, 2);
        s1 += __shfl_xor_sync(0xffffffffu, s1, 1);
        s1 += __shfl_xor_sync(0xffffffffu, s1, 2);
        if (tg == 0) {
            const int r0 = warp_m * 64 + mi * 16 + g;
            sred[warp_n * 128 + r0] = s0;
            sred[warp_n * 128 + r0 + 8] = s1;
        }
    }
    __syncthreads();
    if (tid < 128) {
        float s = sred[tid] + sred[128 + tid] + sred[256 + tid] + sred[384 + tid];
        g_scores[t][rowBase + tid] = s + bias2;
    }
}

// ---------------------------------------------------------------------------
// K2: per-segment softmax stats + weight write.  grid (BATCH, 2)
// ---------------------------------------------------------------------------
__global__ __launch_bounds__(256) void seg_softmax_kernel(
    const int* __restrict__ loff, const int* __restrict__ poff)
{
    const int b = blockIdx.x;
    const int t = blockIdx.y;
    const int* off = t ? poff : loff;
    const int start = b ? off[b - 1] : 0;
    const int end = off[b];
    const float* sc = g_scores[t];
    float* wg = g_wgt[t];
    __shared__ float red[256];
    const int tid = threadIdx.x;

    float m = -1e30f;
    for (int i = start + tid; i < end; i += 256) m = fmaxf(m, sc[i]);
    red[tid] = m; __syncthreads();
    for (int s2 = 128; s2 > 0; s2 >>= 1) {
        if (tid < s2) red[tid] = fmaxf(red[tid], red[tid + s2]);
        __syncthreads();
    }
    m = red[0]; __syncthreads();

    float s = 0.f;
    for (int i = start + tid; i < end; i += 256) s += expf(sc[i] - m);
    red[tid] = s; __syncthreads();
    for (int s2 = 128; s2 > 0; s2 >>= 1) {
        if (tid < s2) red[tid] += red[tid + s2];
        __syncthreads();
    }
    const float inv = 1.f / red[0];
    for (int i = start + tid; i < end; i += 256)
        wg[i] = expf(sc[i] - m) * inv;
}

// ---------------------------------------------------------------------------
// K3: weighted pooling partials. grid (NSLICE, 2*BATCH), block 128.
// Each thread owns 4 channels (float4); weights staged in SMEM.
// ---------------------------------------------------------------------------
__global__ __launch_bounds__(128) void pool_kernel(
    const float* __restrict__ lf, const float* __restrict__ pf,
    const int* __restrict__ loff, const int* __restrict__ poff)
{
    const int sl = blockIdx.x;
    const int bt = blockIdx.y;
    const int b = bt >> 1, t = bt & 1;
    const float* feat = t ? pf : lf;
    const int* off = t ? poff : loff;
    const int start = b ? off[b - 1] : 0;
    const int end = off[b];
    const int cnt = end - start;
    const int per = (cnt + NSLICE - 1) / NSLICE;
    const int i0 = start + sl * per;
    const int i1 = min(i0 + per, end);
    const int c = threadIdx.x * 4;

    __shared__ float sw[256];
    float4 acc = make_float4(0.f, 0.f, 0.f, 0.f);

    for (int base = i0; base < i1; base += 256) {
        const int n = min(256, i1 - base);
        __syncthreads();
        for (int i = threadIdx.x; i < n; i += 128) sw[i] = g_wgt[t][base + i];
        __syncthreads();
        int r = 0;
        for (; r + 4 <= n; r += 4) {
            const float* p0 = feat + (size_t)(base + r) * CDIM + c;
            float4 v0 = *(const float4*)(p0);
            float4 v1 = *(const float4*)(p0 + CDIM);
            float4 v2 = *(const float4*)(p0 + 2 * CDIM);
            float4 v3 = *(const float4*)(p0 + 3 * CDIM);
            const float w0 = sw[r], w1_ = sw[r + 1], w2_ = sw[r + 2], w3 = sw[r + 3];
            acc.x += v0.x * w0 + v1.x * w1_ + v2.x * w2_ + v3.x * w3;
            acc.y += v0.y * w0 + v1.y * w1_ + v2.y * w2_ + v3.y * w3;
            acc.z += v0.z * w0 + v1.z * w1_ + v2.z * w2_ + v3.z * w3;
            acc.w += v0.w * w0 + v1.w * w1_ + v2.w * w2_ + v3.w * w3;
        }
        for (; r < n; r++) {
            float4 v = *(const float4*)(feat + (size_t)(base + r) * CDIM + c);
            const float w = sw[r];
            acc.x += v.x * w; acc.y += v.y * w; acc.z += v.z * w; acc.w += v.w * w;
        }
    }
    *(float4*)&g_part[t][b][sl][c] = acc;
}

// K3b: reduce slices. grid 2*BATCH, block 512.
__global__ __launch_bounds__(512) void pool_reduce_kernel()
{
    const int bt = blockIdx.x;
    const int b = bt >> 1, t = bt & 1;
    const int c = threadIdx.x;
    float s = 0.f;
#pragma unroll
    for (int sl = 0; sl < NSLICE; sl++) s += g_part[t][b][sl][c];
    g_pool[t][b][c] = s;
}

// ---------------------------------------------------------------------------
// K4: regression head. One block per batch row.
// ---------------------------------------------------------------------------
__global__ __launch_bounds__(256) void head_kernel(
    const int* __restrict__ cat_id, const float* __restrict__ cat_emb,
    const float* __restrict__ rw1, const float* __restrict__ rb1,
    const float* __restrict__ g1, const float* __restrict__ be1,
    const float* __restrict__ rw2, const float* __restrict__ rb2,
    const float* __restrict__ g2, const float* __restrict__ be2,
    const float* __restrict__ rw3, const float* __restrict__ rb3,
    float* __restrict__ out)
{
    const int b = blockIdx.x;
    const int tid = threadIdx.x;
    __shared__ float g[FUSE];
    __shared__ float h[H1];
    __shared__ float h2[H2];
    __shared__ float red[256];

    for (int i = tid; i < CDIM; i += 256) {
        g[i] = g_pool[0][b][i];
        g[CDIM + i] = g_pool[1][b][i];
    }
    if (tid < EMB) g[2 * CDIM + tid] = cat_emb[cat_id[b] * EMB + tid];
    __syncthreads();

    float acc = rb1[tid];
    for (int k = 0; k < FUSE; k++) acc += g[k] * rw1[(size_t)k * H1 + tid];

    red[tid] = acc; __syncthreads();
    for (int s = 128; s > 0; s >>= 1) { if (tid < s) red[tid] += red[tid + s]; __syncthreads(); }
    float mu = red[0] / (float)H1; __syncthreads();
    red[tid] = acc * acc; __syncthreads();
    for (int s = 128; s > 0; s >>= 1) { if (tid < s) red[tid] += red[tid + s]; __syncthreads(); }
    float var = red[0] / (float)H1 - mu * mu;
    {
        float v = (acc - mu) * rsqrtf(var + 1e-5f) * g1[tid] + be1[tid];
        h[tid] = v > 0.f ? v : 0.f;
    }
    __syncthreads();

    float acc2 = 0.f;
    if (tid < H2) {
        acc2 = rb2[tid];
        for (int k = 0; k < H1; k++) acc2 += h[k] * rw2[(size_t)k * H2 + tid];
    }
    red[tid] = (tid < H2) ? acc2 : 0.f; __syncthreads();
    for (int s = 128; s > 0; s >>= 1) { if (tid < s) red[tid] += red[tid + s]; __syncthreads(); }
    mu = red[0] / (float)H2; __syncthreads();
    red[tid] = (tid < H2) ? acc2 * acc2 : 0.f; __syncthreads();
    for (int s = 128; s > 0; s >>= 1) { if (tid < s) red[tid] += red[tid + s]; __syncthreads(); }
    var = red[0] / (float)H2 - mu * mu;
    if (tid < H2) {
        float v = (acc2 - mu) * rsqrtf(var + 1e-5f) * g2[tid] + be2[tid];
        h2[tid] = v > 0.f ? v : 0.f;
    }
    __syncthreads();

    if (tid < 3) {
        float o = rb3[tid];
        for (int k = 0; k < H2; k++) o += h2[k] * rw3[k * 3 + tid];
        out[b * 3 + tid] = o;
    }
}

// ---------------------------------------------------------------------------
extern "C" void kernel_launch(void* const* d_in, const int* in_sizes, int n_in,
                              void* d_out, int out_size)
{
    const float* local_feat  = (const float*)d_in[0];
    const float* parent_feat = (const float*)d_in[1];
    const int*   loff        = (const int*)d_in[2];
    const int*   poff        = (const int*)d_in[3];
    const int*   cat_id      = (const int*)d_in[4];
    const float* aw1 = (const float*)d_in[5];
    const float* ab1 = (const float*)d_in[6];
    const float* aw2 = (const float*)d_in[7];
    const float* ab2 = (const float*)d_in[8];
    const float* pw1 = (const float*)d_in[9];
    const float* pb1 = (const float*)d_in[10];
    const float* pw2 = (const float*)d_in[11];
    const float* pb2 = (const float*)d_in[12];
    const float* cemb = (const float*)d_in[13];
    const float* rw1 = (const float*)d_in[14];
    const float* rb1 = (const float*)d_in[15];
    const float* ln1g = (const float*)d_in[16];
    const float* ln1b = (const float*)d_in[17];
    const float* rw2 = (const float*)d_in[18];
    const float* rb2 = (const float*)d_in[19];
    const float* ln2g = (const float*)d_in[20];
    const float* ln2b = (const float*)d_in[21];
    const float* rw3 = (const float*)d_in[22];
    const float* rb3 = (const float*)d_in[23];

    const int nrows = in_sizes[0] / CDIM;   // 131072
    const int gridM = nrows / 128;          // 1024

    cudaFuncSetAttribute(scores_mma_kernel,
                         cudaFuncAttributeMaxDynamicSharedMemorySize, S_TOT);

    scores_mma_kernel<<<dim3(gridM, 2), 256, S_TOT>>>(
        local_feat, parent_feat,
        aw1, ab1, aw2, ab2, pw1, pb1, pw2, pb2);
    seg_softmax_kernel<<<dim3(BATCH, 2), 256>>>(loff, poff);
    pool_kernel<<<dim3(NSLICE, 2 * BATCH), 128>>>(local_feat, parent_feat, loff, poff);
    pool_reduce_kernel<<<2 * BATCH, 512>>>();
    head_kernel<<<BATCH, 256>>>(cat_id, cemb, rw1, rb1, ln1g, ln1b,
                                rw2, rb2, ln2g, ln2b, rw3, rb3, (float*)d_out);
}